// round 15
// baseline (speedup 1.0000x reference)
#include <cuda_runtime.h>
#include <cuda_fp16.h>

#define HW 65536

// ---- scratch (device globals; all intermediates fp16) ----
__device__ __half g_qi [8 * HW * 8];     // [B][h*w][8c]  16B/pixel
__device__ __half g_ki [8 * HW * 8];
__device__ __half g_vi [8 * HW * 64];    // [B][h*w][64c] 128B/pixel (one L2 line)
__device__ __half g_hT [8 * 64 * HW];    // column-attn out, [B][C][w][h] planar
__device__ __half g_w  [8 * 64 * HW];    // row-attn out,    [B][C][h][w] planar

// ---- packed fp32x2 (proj) ----
__device__ __forceinline__ unsigned long long pk2(float lo, float hi) {
    unsigned long long r;
    asm("mov.b64 %0, {%1, %2};" : "=l"(r) : "f"(lo), "f"(hi));
    return r;
}
__device__ __forceinline__ float2 upk2(unsigned long long v) {
    float2 f;
    asm("mov.b64 {%0, %1}, %2;" : "=f"(f.x), "=f"(f.y) : "l"(v));
    return f;
}
__device__ __forceinline__ unsigned long long ffma2(unsigned long long a,
                                                    unsigned long long b,
                                                    unsigned long long c) {
    unsigned long long d;
    asm("fma.rn.f32x2 %0, %1, %2, %3;" : "=l"(d) : "l"(a), "l"(b), "l"(c));
    return d;
}

// ---- warp MMA helpers (baseline PTX: valid on plain sm_103 target) ----
__device__ __forceinline__ unsigned smem_u32(const void* p) {
    unsigned a;
    asm("{ .reg .u64 t; cvta.to.shared.u64 t, %1; cvt.u32.u64 %0, t; }"
        : "=r"(a) : "l"(p));
    return a;
}
__device__ __forceinline__ void ldsm_x4(unsigned addr, unsigned& r0, unsigned& r1,
                                        unsigned& r2, unsigned& r3) {
    asm volatile("ldmatrix.sync.aligned.m8n8.x4.shared.b16 {%0,%1,%2,%3}, [%4];"
                 : "=r"(r0), "=r"(r1), "=r"(r2), "=r"(r3) : "r"(addr));
}
__device__ __forceinline__ void ldsm_x4_t(unsigned addr, unsigned& r0, unsigned& r1,
                                          unsigned& r2, unsigned& r3) {
    asm volatile("ldmatrix.sync.aligned.m8n8.x4.trans.shared.b16 {%0,%1,%2,%3}, [%4];"
                 : "=r"(r0), "=r"(r1), "=r"(r2), "=r"(r3) : "r"(addr));
}
__device__ __forceinline__ void ldsm_x2(unsigned addr, unsigned& r0, unsigned& r1) {
    asm volatile("ldmatrix.sync.aligned.m8n8.x2.shared.b16 {%0,%1}, [%2];"
                 : "=r"(r0), "=r"(r1) : "r"(addr));
}
__device__ __forceinline__ void mma16816(float* d, unsigned a0, unsigned a1,
                                         unsigned a2, unsigned a3,
                                         unsigned b0, unsigned b1) {
    asm volatile(
        "mma.sync.aligned.m16n8k16.row.col.f32.f16.f16.f32 "
        "{%0,%1,%2,%3},{%4,%5,%6,%7},{%8,%9},{%0,%1,%2,%3};"
        : "+f"(d[0]), "+f"(d[1]), "+f"(d[2]), "+f"(d[3])
        : "r"(a0), "r"(a1), "r"(a2), "r"(a3), "r"(b0), "r"(b1));
}
__device__ __forceinline__ void mma16808(float& d0, float& d1, float& d2, float& d3,
                                         unsigned a0, unsigned a1, unsigned b0) {
    asm volatile(
        "mma.sync.aligned.m16n8k8.row.col.f32.f16.f16.f32 "
        "{%0,%1,%2,%3},{%4,%5},{%6},{%7,%8,%9,%10};"
        : "=f"(d0), "=f"(d1), "=f"(d2), "=f"(d3)
        : "r"(a0), "r"(a1), "r"(b0),
          "f"(0.f), "f"(0.f), "f"(0.f), "f"(0.f));
}
__device__ __forceinline__ unsigned ex2_f16x2(unsigned x) {
    unsigned r;
    asm("ex2.approx.f16x2 %0, %1;" : "=r"(r) : "r"(x));
    return r;
}

// ---- K1a: q/k projections (16 outputs/thread -> ~45 regs, high occ) ----
__global__ __launch_bounds__(256) void proj_qk(
    const float* __restrict__ x,
    const float* __restrict__ Wq, const float* __restrict__ bq,
    const float* __restrict__ Wk, const float* __restrict__ bk)
{
    __shared__ float ws[64][16];
    __shared__ float bs[16];
    int tid = threadIdx.x;
    for (int idx = tid; idx < 64 * 16; idx += 256) {
        int c = idx >> 4, o = idx & 15;
        ws[c][o] = (o < 8) ? Wq[o * 64 + c] : Wk[(o - 8) * 64 + c];
    }
    if (tid < 16) bs[tid] = (tid < 8) ? bq[tid] : bk[tid - 8];
    __syncthreads();

    int p  = blockIdx.x * 256 + tid;
    int b  = p >> 16;
    int hw = p & 65535;
    const float* xp = x + ((long)(b * 64) << 16) + hw;

    unsigned long long av[8];
    #pragma unroll
    for (int o = 0; o < 8; o++) av[o] = pk2(bs[2 * o], bs[2 * o + 1]);

    #pragma unroll 8
    for (int c = 0; c < 64; c++) {
        float xv = xp[c << 16];
        unsigned long long x2 = pk2(xv, xv);
        const unsigned long long* wr = (const unsigned long long*)(&ws[c][0]);
        #pragma unroll
        for (int o = 0; o < 8; o++) av[o] = ffma2(wr[o], x2, av[o]);
    }

    {
        uint4 u; unsigned* uu = &u.x;
        #pragma unroll
        for (int t = 0; t < 4; t++) {
            float2 f = upk2(av[t]);
            __half2 h = __floats2half2_rn(f.x, f.y);
            uu[t] = *(unsigned*)&h;
        }
        ((uint4*)g_qi)[p] = u;
        #pragma unroll
        for (int t = 0; t < 4; t++) {
            float2 f = upk2(av[4 + t]);
            __half2 h = __floats2half2_rn(f.x, f.y);
            uu[t] = *(unsigned*)&h;
        }
        ((uint4*)g_ki)[p] = u;
    }
}

// ---- K1b: v projection (2 threads/pixel, 32 outputs each -> ~65 regs) ----
__global__ __launch_bounds__(512) void proj_v(
    const float* __restrict__ x,
    const float* __restrict__ Wv, const float* __restrict__ bv)
{
    __shared__ float ws[64][64];
    __shared__ float bs[64];
    int tid = threadIdx.x;
    for (int idx = tid; idx < 4096; idx += 512) {
        int c = idx >> 6, o = idx & 63;
        ws[c][o] = Wv[o * 64 + c];
    }
    if (tid < 64) bs[tid] = bv[tid];
    __syncthreads();

    int pl = tid >> 1, h = tid & 1;       // pixel-local, output half
    int p  = blockIdx.x * 256 + pl;
    int b  = p >> 16;
    int hw = p & 65535;
    const float* xp = x + ((long)(b * 64) << 16) + hw;
    int ob = h << 5;                       // output base: 0 or 32

    unsigned long long av[16];
    #pragma unroll
    for (int o = 0; o < 16; o++) av[o] = pk2(bs[ob + 2 * o], bs[ob + 2 * o + 1]);

    #pragma unroll 8
    for (int c = 0; c < 64; c++) {
        float xv = xp[c << 16];
        unsigned long long x2 = pk2(xv, xv);
        const unsigned long long* wr = (const unsigned long long*)(&ws[c][ob]);
        #pragma unroll
        for (int o = 0; o < 16; o++) av[o] = ffma2(wr[o], x2, av[o]);
    }

    // store this thread's 64B of the pixel's 128B interleaved v-line
    uint4* gv = (uint4*)g_vi + (long)p * 8 + h * 4;
    #pragma unroll
    for (int s = 0; s < 4; s++) {
        uint4 u; unsigned* uu = &u.x;
        #pragma unroll
        for (int t = 0; t < 4; t++) {
            float2 f = upk2(av[4 * s + t]);
            __half2 hh = __floats2half2_rn(f.x, f.y);
            uu[t] = *(unsigned*)&hh;
        }
        gv[s] = u;
    }
}

// ---- K2: line attention; MMA max + ex2 exp + HMMA GEMMs; no transposes ----
// smem (bytes), total 113664 -> 2 CTAs/SM:
#define OFF_KT   0        // fp16 kT [j=256][c=8], 16B rows     (4096)
                          //   (reused as PB l-partials after pba regs load)
#define OFF_QTC  4096     // fp16 qT chunk [i=128][c=8]         (2048)
#define OFF_V    6144     // fp16 V [i=256][64c], stride 144B   (36864)
#define OFF_PT   43008    // fp16 P^T [j=256][stride 272B]      (69632)
                          //   (also qT-full borrow in max phase; fp16 O staging)
#define OFF_SMAX 112640   // fp16 m*log2e [256]                 (512)
#define OFF_SL   113152   // fp32 1/l [128]                     (512)
#define ATTN_SMEM 113664

__global__ __launch_bounds__(512, 2) void attn_kernel()
{
    extern __shared__ char smem[];
    unsigned sbase = smem_u32(smem);

    int mode = blockIdx.x >> 11;
    int n    = blockIdx.x & 2047;
    int b    = n >> 8, line = n & 255;

    long qkoff = (long)b * HW + (mode ? line : (line << 8));
    const uint4* qp = (const uint4*)g_qi + qkoff;
    const uint4* kp = (const uint4*)g_ki + qkoff;
    const uint4* vp = (const uint4*)g_vi + qkoff * 8;
    int qs = mode ? 256 : 1;
    int vs = mode ? 2048 : 8;
    __half* o0 = ((mode == 0) ? g_w : g_hT) + ((long)(b * 64) << 16) + (line << 8);

    int tid  = threadIdx.x;
    int wid  = tid >> 5;
    int lane = tid & 31;
    int gid = lane >> 2, tid2 = lane & 3;
    const float L2E = 1.4426950408889634f;

    // ---- loads: kT (tid<256), qT-full borrow (tid>=256), V rows (all) ----
    if (tid < 256) {
        ((uint4*)(smem + OFF_KT))[tid] = kp[tid * qs];
    } else {
        ((uint4*)(smem + OFF_PT))[tid - 256] = qp[(tid - 256) * qs];
    }
    for (int idx = tid; idx < 2048; idx += 512) {
        int row = idx >> 3, seg = idx & 7;
        *(uint4*)(smem + OFF_V + row * 144 + seg * 16) = vp[row * vs + seg];
    }
    __syncthreads();

    // ---- max phase (m=i): warp owns 16 i rows; true row max in registers ----
    {
        unsigned a0, a1;
        ldsm_x2(sbase + OFF_PT + (unsigned)((wid * 16 + (lane & 15)) * 16), a0, a1);
        float r0 = -1e30f, r2 = -1e30f;
        #pragma unroll
        for (int t4 = 0; t4 < 8; t4++) {
            unsigned b0, b1, b2, b3;
            ldsm_x4(sbase + OFF_KT + (unsigned)((t4 * 32 + lane) * 16), b0, b1, b2, b3);
            #pragma unroll
            for (int tt = 0; tt < 4; tt++) {
                unsigned bb = (tt == 0) ? b0 : (tt == 1) ? b1 : (tt == 2) ? b2 : b3;
                float d0, d1, d2, d3;
                mma16808(d0, d1, d2, d3, a0, a1, bb);
                r0 = fmaxf(r0, fmaxf(d0, d1));
                r2 = fmaxf(r2, fmaxf(d2, d3));
            }
        }
        r0 = fmaxf(r0, __shfl_xor_sync(0xffffffffu, r0, 1));
        r0 = fmaxf(r0, __shfl_xor_sync(0xffffffffu, r0, 2));
        r2 = fmaxf(r2, __shfl_xor_sync(0xffffffffu, r2, 1));
        r2 = fmaxf(r2, __shfl_xor_sync(0xffffffffu, r2, 2));
        if (tid2 == 0) {
            __half* sm = (__half*)(smem + OFF_SMAX);
            sm[wid * 16 + gid]     = __float2half_rn(r0 * L2E);
            sm[wid * 16 + gid + 8] = __float2half_rn(r2 * L2E);
        }
    }
    __syncthreads();

    // ---- O-GEMM tiling (fixed across chunks) ----
    int mc = wid & 3, jc = wid >> 2;
    int at_row = (lane & 7) + ((lane >> 4) & 1) * 8;
    unsigned abase = sbase + OFF_V + (unsigned)at_row * 144u
                   + (unsigned)(mc * 32 + ((lane >> 3) & 1) * 16);
    unsigned brow  = (unsigned)((lane & 7) + ((lane >> 4) ? 8 : 0));
    unsigned bbase = sbase + OFF_PT + ((unsigned)(jc * 64) + brow) * 272u
                   + (unsigned)((lane >> 3) & 1) * 16u;

    float acc[8][4];
    #pragma unroll
    for (int nt = 0; nt < 8; nt++)
        #pragma unroll
        for (int t = 0; t < 4; t++) acc[nt][t] = 0.f;

    // exp-phase A operand (kT rows for warp's 16 j) — KT dead afterwards
    unsigned pba0, pba1;
    ldsm_x2(sbase + OFF_KT + (unsigned)((wid * 16 + (lane & 15)) * 16), pba0, pba1);

    for (int chunk = 0; chunk < 2; chunk++) {
        if (tid < 128)
            ((uint4*)(smem + OFF_QTC))[tid] = qp[((chunk << 7) + tid) * qs];
        __syncthreads();

        // ---- exp phase (m=j, n=i): P^T[j][i] = 2^(S*l2e - m*l2e); col sums ----
        {
            const __half* smx = (const __half*)(smem + OFF_SMAX) + (chunk << 7);
            __half* pb = (__half*)(smem + OFF_KT);   // PB overlays dead KT
            char* prow0 = smem + OFF_PT + (wid * 16 + gid) * 272 + tid2 * 4;
            char* prow8 = prow0 + 8 * 272;
            #pragma unroll
            for (int t4 = 0; t4 < 4; t4++) {
                unsigned b0, b1, b2, b3;
                ldsm_x4(sbase + OFF_QTC + (unsigned)((t4 * 32 + lane) * 16),
                        b0, b1, b2, b3);
                #pragma unroll
                for (int tt = 0; tt < 4; tt++) {
                    unsigned bb = (tt == 0) ? b0 : (tt == 1) ? b1 : (tt == 2) ? b2 : b3;
                    int t = t4 * 4 + tt;
                    float d0, d1, d2, d3;
                    mma16808(d0, d1, d2, d3, pba0, pba1, bb);
                    int iA = t * 8 + tid2 * 2;
                    float2 mf = __half22float2(*(const __half2*)(smx + iA));
                    float f0 = fmaf(d0, L2E, -mf.x);
                    float f1 = fmaf(d1, L2E, -mf.y);
                    float f2 = fmaf(d2, L2E, -mf.x);
                    float f3 = fmaf(d3, L2E, -mf.y);
                    __half2 h01 = __floats2half2_rn(f0, f1);
                    __half2 h23 = __floats2half2_rn(f2, f3);
                    unsigned e01 = ex2_f16x2(*(unsigned*)&h01);
                    unsigned e23 = ex2_f16x2(*(unsigned*)&h23);
                    *(unsigned*)(prow0 + t * 16) = e01;
                    *(unsigned*)(prow8 + t * 16) = e23;
                    __half2 cs = __hadd2(*(__half2*)&e01, *(__half2*)&e23);
                    unsigned csu = *(unsigned*)&cs;
                    unsigned o4  = __shfl_xor_sync(0xffffffffu, csu, 4);
                    cs = __hadd2(cs, *(__half2*)&o4);  csu = *(unsigned*)&cs;
                    unsigned o8  = __shfl_xor_sync(0xffffffffu, csu, 8);
                    cs = __hadd2(cs, *(__half2*)&o8);  csu = *(unsigned*)&cs;
                    unsigned o16 = __shfl_xor_sync(0xffffffffu, csu, 16);
                    cs = __hadd2(cs, *(__half2*)&o16); csu = *(unsigned*)&cs;
                    if (gid == 0)
                        *(unsigned*)(pb + wid * 128 + iA) = csu;
                }
            }
        }
        __syncthreads();

        // reduce l partials -> 1/l
        if (tid < 128) {
            float s = 0.f;
            #pragma unroll
            for (int w = 0; w < 16; w++)
                s += __half2float(((__half*)(smem + OFF_KT))[w * 128 + tid]);
            ((float*)(smem + OFF_SL))[tid] = 1.0f / s;
        }
        __syncthreads();

        // fold 1/l_i into V row i (scalar per 128B row, conflict-free)
        {
            const float* sl = (const float*)(smem + OFF_SL);
            for (int idx = tid; idx < 4096; idx += 512) {
                int rl = idx >> 5, w = idx & 31;
                __half2* vv = (__half2*)(smem + OFF_V + ((chunk << 7) + rl) * 144 + w * 4);
                *vv = __hmul2(*vv, __float2half2_rn(sl[rl]));
            }
        }
        __syncthreads();

        // O-GEMM K-chunk: acc += V'[c][k] * P^T[j][k]  (A via trans ldmatrix)
        {
            unsigned aaddr = abase + (unsigned)(chunk * 128) * 144u;
            #pragma unroll
            for (int kk = 0; kk < 8; kk++) {
                unsigned a0, a1, a2, a3;
                ldsm_x4_t(aaddr + (unsigned)(kk * 16) * 144u, a0, a1, a2, a3);
                #pragma unroll
                for (int g = 0; g < 4; g++) {
                    unsigned b0, b1, b2, b3;
                    ldsm_x4(bbase + (unsigned)g * (16u * 272u) + (unsigned)kk * 32u,
                            b0, b1, b2, b3);
                    mma16816(acc[2 * g],     a0, a1, a2, a3, b0, b1);
                    mma16816(acc[2 * g + 1], a0, a1, a2, a3, b2, b3);
                }
            }
        }
        __syncthreads();
    }

    // ---- stage O fp16 in smem (reuse PT, stride 264 halfs), coalesced store ----
    {
        __half* so = (__half*)(smem + OFF_PT);
        int crow = mc * 16 + gid;
        int jb2  = jc * 64 + tid2 * 2;
        #pragma unroll
        for (int nt = 0; nt < 8; nt++) {
            int j = jb2 + nt * 8;
            *(__half2*)(so + crow * 264 + j)       = __floats2half2_rn(acc[nt][0], acc[nt][1]);
            *(__half2*)(so + (crow + 8) * 264 + j) = __floats2half2_rn(acc[nt][2], acc[nt][3]);
        }
        __syncthreads();
        for (int idx = tid; idx < 2048; idx += 512) {
            int c = idx >> 5, seg = idx & 31;
            ((uint4*)(o0 + (c << 16)))[seg] = *(uint4*)(so + c * 264 + seg * 8);
        }
    }
}

// ---- K3: out = gamma*(h_out + w_out) + x (fp16 h/w, fp32 out) ----
__global__ void combine_kernel(const float* __restrict__ x,
                               const float* __restrict__ gamma,
                               float* __restrict__ out)
{
    __shared__ __half t[32][33];
    int plane = blockIdx.z;
    const __half* hT = g_hT + ((long)plane << 16);
    const __half* wf = g_w  + ((long)plane << 16);
    const float*  xp = x    + ((long)plane << 16);
    float*        op = out  + ((long)plane << 16);
    int h0 = blockIdx.y << 5, w0 = blockIdx.x << 5;
    int tx = threadIdx.x, ty = threadIdx.y;
    float g = gamma[0];
    #pragma unroll
    for (int yy = 0; yy < 32; yy += 8)
        t[ty + yy][tx] = hT[(w0 + ty + yy) * 256 + h0 + tx];
    __syncthreads();
    #pragma unroll
    for (int yy = 0; yy < 32; yy += 8) {
        int idx = (h0 + ty + yy) * 256 + w0 + tx;
        op[idx] = fmaf(g, __half2float(t[tx][ty + yy]) + __half2float(wf[idx]), xp[idx]);
    }
}

extern "C" void kernel_launch(void* const* d_in, const int* in_sizes, int n_in,
                              void* d_out, int out_size) {
    const float* x     = (const float*)d_in[0];
    const float* Wq    = (const float*)d_in[1];
    const float* bq    = (const float*)d_in[2];
    const float* Wk    = (const float*)d_in[3];
    const float* bk    = (const float*)d_in[4];
    const float* Wv    = (const float*)d_in[5];
    const float* bv    = (const float*)d_in[6];
    const float* gamma = (const float*)d_in[7];
    float* out = (float*)d_out;

    cudaFuncSetAttribute(attn_kernel,
                         cudaFuncAttributeMaxDynamicSharedMemorySize, ATTN_SMEM);

    proj_qk<<<2048, 256>>>(x, Wq, bq, Wk, bk);
    proj_v<<<2048, 512>>>(x, Wv, bv);
    attn_kernel<<<4096, 512, ATTN_SMEM>>>();
    combine_kernel<<<dim3(8, 8, 512), dim3(32, 8)>>>(x, gamma, out);
}

// round 16
// speedup vs baseline: 1.0649x; 1.0649x over previous
#include <cuda_runtime.h>
#include <cuda_fp16.h>

#define HW 65536

// ---- scratch (device globals; all intermediates fp16) ----
__device__ __half g_qi [8 * HW * 8];     // [B][h*w][8c]  16B/pixel
__device__ __half g_ki [8 * HW * 8];
__device__ __half g_vi [8 * HW * 64];    // [B][h*w][64c] 128B/pixel (one L2 line)
__device__ __half g_hT [8 * 64 * HW];    // column-attn out, [B][C][w][h] planar
__device__ __half g_w  [8 * 64 * HW];    // row-attn out,    [B][C][h][w] planar

// ---- packed fp32x2 (proj) ----
__device__ __forceinline__ unsigned long long pk2(float lo, float hi) {
    unsigned long long r;
    asm("mov.b64 %0, {%1, %2};" : "=l"(r) : "f"(lo), "f"(hi));
    return r;
}
__device__ __forceinline__ float2 upk2(unsigned long long v) {
    float2 f;
    asm("mov.b64 {%0, %1}, %2;" : "=f"(f.x), "=f"(f.y) : "l"(v));
    return f;
}
__device__ __forceinline__ unsigned long long ffma2(unsigned long long a,
                                                    unsigned long long b,
                                                    unsigned long long c) {
    unsigned long long d;
    asm("fma.rn.f32x2 %0, %1, %2, %3;" : "=l"(d) : "l"(a), "l"(b), "l"(c));
    return d;
}

// ---- warp MMA helpers (baseline PTX: valid on plain sm_103 target) ----
__device__ __forceinline__ unsigned smem_u32(const void* p) {
    unsigned a;
    asm("{ .reg .u64 t; cvta.to.shared.u64 t, %1; cvt.u32.u64 %0, t; }"
        : "=r"(a) : "l"(p));
    return a;
}
__device__ __forceinline__ void ldsm_x4(unsigned addr, unsigned& r0, unsigned& r1,
                                        unsigned& r2, unsigned& r3) {
    asm volatile("ldmatrix.sync.aligned.m8n8.x4.shared.b16 {%0,%1,%2,%3}, [%4];"
                 : "=r"(r0), "=r"(r1), "=r"(r2), "=r"(r3) : "r"(addr));
}
__device__ __forceinline__ void ldsm_x4_t(unsigned addr, unsigned& r0, unsigned& r1,
                                          unsigned& r2, unsigned& r3) {
    asm volatile("ldmatrix.sync.aligned.m8n8.x4.trans.shared.b16 {%0,%1,%2,%3}, [%4];"
                 : "=r"(r0), "=r"(r1), "=r"(r2), "=r"(r3) : "r"(addr));
}
__device__ __forceinline__ void ldsm_x2(unsigned addr, unsigned& r0, unsigned& r1) {
    asm volatile("ldmatrix.sync.aligned.m8n8.x2.shared.b16 {%0,%1}, [%2];"
                 : "=r"(r0), "=r"(r1) : "r"(addr));
}
__device__ __forceinline__ void mma16816(float* d, unsigned a0, unsigned a1,
                                         unsigned a2, unsigned a3,
                                         unsigned b0, unsigned b1) {
    asm volatile(
        "mma.sync.aligned.m16n8k16.row.col.f32.f16.f16.f32 "
        "{%0,%1,%2,%3},{%4,%5,%6,%7},{%8,%9},{%0,%1,%2,%3};"
        : "+f"(d[0]), "+f"(d[1]), "+f"(d[2]), "+f"(d[3])
        : "r"(a0), "r"(a1), "r"(a2), "r"(a3), "r"(b0), "r"(b1));
}
__device__ __forceinline__ void mma16808(float& d0, float& d1, float& d2, float& d3,
                                         unsigned a0, unsigned a1, unsigned b0) {
    asm volatile(
        "mma.sync.aligned.m16n8k8.row.col.f32.f16.f16.f32 "
        "{%0,%1,%2,%3},{%4,%5},{%6},{%7,%8,%9,%10};"
        : "=f"(d0), "=f"(d1), "=f"(d2), "=f"(d3)
        : "r"(a0), "r"(a1), "r"(b0),
          "f"(0.f), "f"(0.f), "f"(0.f), "f"(0.f));
}
__device__ __forceinline__ unsigned ex2_f16x2(unsigned x) {
    unsigned r;
    asm("ex2.approx.f16x2 %0, %1;" : "=r"(r) : "r"(x));
    return r;
}

// ---- K1a: q/k projections; thread = 4 pixels x 4 outputs (weight LDS /4) ----
__global__ __launch_bounds__(256) void proj_qk(
    const float* __restrict__ x,
    const float* __restrict__ Wq, const float* __restrict__ bq,
    const float* __restrict__ Wk, const float* __restrict__ bk)
{
    __shared__ float ws[64][16];
    __shared__ float bs[16];
    int tid = threadIdx.x;
    for (int idx = tid; idx < 64 * 16; idx += 256) {
        int c = idx >> 4, o = idx & 15;
        ws[c][o] = (o < 8) ? Wq[o * 64 + c] : Wk[(o - 8) * 64 + c];
    }
    if (tid < 16) bs[tid] = (tid < 8) ? bq[tid] : bk[tid - 8];
    __syncthreads();

    int quad = tid >> 2, grp = tid & 3;        // grp: 4 outputs of the 16
    int b  = blockIdx.x >> 8;
    int hw = ((blockIdx.x & 255) << 8) + (quad << 2);
    const float4* xp = (const float4*)(x + ((long)(b * 64) << 16) + hw);

    unsigned long long av[4][2];
    {
        unsigned long long b0 = pk2(bs[grp * 4],     bs[grp * 4 + 1]);
        unsigned long long b1 = pk2(bs[grp * 4 + 2], bs[grp * 4 + 3]);
        #pragma unroll
        for (int px = 0; px < 4; px++) { av[px][0] = b0; av[px][1] = b1; }
    }

    #pragma unroll 4
    for (int c = 0; c < 64; c++) {
        float4 xv = xp[c << 14];               // channel stride = 16384 float4
        const unsigned long long* wr = (const unsigned long long*)(&ws[c][grp * 4]);
        unsigned long long w0 = wr[0], w1 = wr[1];
        unsigned long long x0 = pk2(xv.x, xv.x);
        av[0][0] = ffma2(w0, x0, av[0][0]); av[0][1] = ffma2(w1, x0, av[0][1]);
        unsigned long long x1 = pk2(xv.y, xv.y);
        av[1][0] = ffma2(w0, x1, av[1][0]); av[1][1] = ffma2(w1, x1, av[1][1]);
        unsigned long long x2 = pk2(xv.z, xv.z);
        av[2][0] = ffma2(w0, x2, av[2][0]); av[2][1] = ffma2(w1, x2, av[2][1]);
        unsigned long long x3 = pk2(xv.w, xv.w);
        av[3][0] = ffma2(w0, x3, av[3][0]); av[3][1] = ffma2(w1, x3, av[3][1]);
    }

    int p = (blockIdx.x << 8) + (quad << 2);
    #pragma unroll
    for (int px = 0; px < 4; px++) {
        float2 f0 = upk2(av[px][0]), f1 = upk2(av[px][1]);
        __half2 h0 = __floats2half2_rn(f0.x, f0.y);
        __half2 h1 = __floats2half2_rn(f1.x, f1.y);
        uint2 u;
        u.x = *(unsigned*)&h0; u.y = *(unsigned*)&h1;
        if (grp < 2) ((uint2*)g_qi)[(long)(p + px) * 2 + grp]       = u;
        else         ((uint2*)g_ki)[(long)(p + px) * 2 + (grp - 2)] = u;
    }
}

// ---- K1b: v projection; thread = 4 pixels x 8 outputs (weight LDS /4) ----
__global__ __launch_bounds__(512) void proj_v(
    const float* __restrict__ x,
    const float* __restrict__ Wv, const float* __restrict__ bv)
{
    __shared__ float ws[64][64];
    __shared__ float bs[64];
    int tid = threadIdx.x;
    for (int idx = tid; idx < 4096; idx += 512) {
        int c = idx >> 6, o = idx & 63;
        ws[c][o] = Wv[o * 64 + c];
    }
    if (tid < 64) bs[tid] = bv[tid];
    __syncthreads();

    int quad = tid >> 3, og = tid & 7;         // og: 8 outputs of the 64
    int b  = blockIdx.x >> 8;
    int hw = ((blockIdx.x & 255) << 8) + (quad << 2);
    const float4* xp = (const float4*)(x + ((long)(b * 64) << 16) + hw);

    unsigned long long av[4][4];
    #pragma unroll
    for (int o4 = 0; o4 < 4; o4++) {
        unsigned long long bi = pk2(bs[og * 8 + 2 * o4], bs[og * 8 + 2 * o4 + 1]);
        #pragma unroll
        for (int px = 0; px < 4; px++) av[px][o4] = bi;
    }

    #pragma unroll 4
    for (int c = 0; c < 64; c++) {
        float4 xv = xp[c << 14];
        const unsigned long long* wr = (const unsigned long long*)(&ws[c][og * 8]);
        unsigned long long w0 = wr[0], w1 = wr[1], w2 = wr[2], w3 = wr[3];
        unsigned long long x0 = pk2(xv.x, xv.x);
        av[0][0] = ffma2(w0, x0, av[0][0]); av[0][1] = ffma2(w1, x0, av[0][1]);
        av[0][2] = ffma2(w2, x0, av[0][2]); av[0][3] = ffma2(w3, x0, av[0][3]);
        unsigned long long x1 = pk2(xv.y, xv.y);
        av[1][0] = ffma2(w0, x1, av[1][0]); av[1][1] = ffma2(w1, x1, av[1][1]);
        av[1][2] = ffma2(w2, x1, av[1][2]); av[1][3] = ffma2(w3, x1, av[1][3]);
        unsigned long long x2 = pk2(xv.z, xv.z);
        av[2][0] = ffma2(w0, x2, av[2][0]); av[2][1] = ffma2(w1, x2, av[2][1]);
        av[2][2] = ffma2(w2, x2, av[2][2]); av[2][3] = ffma2(w3, x2, av[2][3]);
        unsigned long long x3 = pk2(xv.w, xv.w);
        av[3][0] = ffma2(w0, x3, av[3][0]); av[3][1] = ffma2(w1, x3, av[3][1]);
        av[3][2] = ffma2(w2, x3, av[3][2]); av[3][3] = ffma2(w3, x3, av[3][3]);
    }

    int p = (blockIdx.x << 8) + (quad << 2);
    #pragma unroll
    for (int px = 0; px < 4; px++) {
        uint4 u; unsigned* uu = &u.x;
        #pragma unroll
        for (int o4 = 0; o4 < 4; o4++) {
            float2 f = upk2(av[px][o4]);
            __half2 h = __floats2half2_rn(f.x, f.y);
            uu[o4] = *(unsigned*)&h;
        }
        ((uint4*)g_vi)[(long)(p + px) * 8 + og] = u;
    }
}

// ---- K2: line attention; MMA max + ex2 exp + HMMA GEMMs; no transposes ----
// smem (bytes), total 113664 -> 2 CTAs/SM:
#define OFF_KT   0        // fp16 kT [j=256][c=8], 16B rows     (4096)
                          //   (reused as PB l-partials after pba regs load)
#define OFF_QTC  4096     // fp16 qT chunk [i=128][c=8]         (2048)
#define OFF_V    6144     // fp16 V [i=256][64c], stride 144B   (36864)
#define OFF_PT   43008    // fp16 P^T [j=256][stride 272B]      (69632)
                          //   (also qT-full borrow in max phase; fp16 O staging)
#define OFF_SMAX 112640   // fp16 m*log2e [256]                 (512)
#define OFF_SL   113152   // fp32 1/l [128]                     (512)
#define ATTN_SMEM 113664

__global__ __launch_bounds__(512, 2) void attn_kernel()
{
    extern __shared__ char smem[];
    unsigned sbase = smem_u32(smem);

    int mode = blockIdx.x >> 11;
    int n    = blockIdx.x & 2047;
    int b    = n >> 8, line = n & 255;

    long qkoff = (long)b * HW + (mode ? line : (line << 8));
    const uint4* qp = (const uint4*)g_qi + qkoff;
    const uint4* kp = (const uint4*)g_ki + qkoff;
    const uint4* vp = (const uint4*)g_vi + qkoff * 8;
    int qs = mode ? 256 : 1;
    int vs = mode ? 2048 : 8;
    __half* o0 = ((mode == 0) ? g_w : g_hT) + ((long)(b * 64) << 16) + (line << 8);

    int tid  = threadIdx.x;
    int wid  = tid >> 5;
    int lane = tid & 31;
    int gid = lane >> 2, tid2 = lane & 3;
    const float L2E = 1.4426950408889634f;

    // ---- loads: kT (tid<256), qT-full borrow (tid>=256), V rows (all) ----
    if (tid < 256) {
        ((uint4*)(smem + OFF_KT))[tid] = kp[tid * qs];
    } else {
        ((uint4*)(smem + OFF_PT))[tid - 256] = qp[(tid - 256) * qs];
    }
    for (int idx = tid; idx < 2048; idx += 512) {
        int row = idx >> 3, seg = idx & 7;
        *(uint4*)(smem + OFF_V + row * 144 + seg * 16) = vp[row * vs + seg];
    }
    __syncthreads();

    // ---- max phase (m=i): warp owns 16 i rows; true row max in registers ----
    {
        unsigned a0, a1;
        ldsm_x2(sbase + OFF_PT + (unsigned)((wid * 16 + (lane & 15)) * 16), a0, a1);
        float r0 = -1e30f, r2 = -1e30f;
        #pragma unroll
        for (int t4 = 0; t4 < 8; t4++) {
            unsigned b0, b1, b2, b3;
            ldsm_x4(sbase + OFF_KT + (unsigned)((t4 * 32 + lane) * 16), b0, b1, b2, b3);
            #pragma unroll
            for (int tt = 0; tt < 4; tt++) {
                unsigned bb = (tt == 0) ? b0 : (tt == 1) ? b1 : (tt == 2) ? b2 : b3;
                float d0, d1, d2, d3;
                mma16808(d0, d1, d2, d3, a0, a1, bb);
                r0 = fmaxf(r0, fmaxf(d0, d1));
                r2 = fmaxf(r2, fmaxf(d2, d3));
            }
        }
        r0 = fmaxf(r0, __shfl_xor_sync(0xffffffffu, r0, 1));
        r0 = fmaxf(r0, __shfl_xor_sync(0xffffffffu, r0, 2));
        r2 = fmaxf(r2, __shfl_xor_sync(0xffffffffu, r2, 1));
        r2 = fmaxf(r2, __shfl_xor_sync(0xffffffffu, r2, 2));
        if (tid2 == 0) {
            __half* sm = (__half*)(smem + OFF_SMAX);
            sm[wid * 16 + gid]     = __float2half_rn(r0 * L2E);
            sm[wid * 16 + gid + 8] = __float2half_rn(r2 * L2E);
        }
    }
    __syncthreads();

    // ---- O-GEMM tiling (fixed across chunks) ----
    int mc = wid & 3, jc = wid >> 2;
    int at_row = (lane & 7) + ((lane >> 4) & 1) * 8;
    unsigned abase = sbase + OFF_V + (unsigned)at_row * 144u
                   + (unsigned)(mc * 32 + ((lane >> 3) & 1) * 16);
    unsigned brow  = (unsigned)((lane & 7) + ((lane >> 4) ? 8 : 0));
    unsigned bbase = sbase + OFF_PT + ((unsigned)(jc * 64) + brow) * 272u
                   + (unsigned)((lane >> 3) & 1) * 16u;

    float acc[8][4];
    #pragma unroll
    for (int nt = 0; nt < 8; nt++)
        #pragma unroll
        for (int t = 0; t < 4; t++) acc[nt][t] = 0.f;

    // exp-phase A operand (kT rows for warp's 16 j) — KT dead afterwards
    unsigned pba0, pba1;
    ldsm_x2(sbase + OFF_KT + (unsigned)((wid * 16 + (lane & 15)) * 16), pba0, pba1);

    for (int chunk = 0; chunk < 2; chunk++) {
        if (tid < 128)
            ((uint4*)(smem + OFF_QTC))[tid] = qp[((chunk << 7) + tid) * qs];
        __syncthreads();

        // ---- exp phase (m=j, n=i): P^T[j][i] = 2^(S*l2e - m*l2e); col sums ----
        {
            const __half* smx = (const __half*)(smem + OFF_SMAX) + (chunk << 7);
            __half* pb = (__half*)(smem + OFF_KT);   // PB overlays dead KT
            char* prow0 = smem + OFF_PT + (wid * 16 + gid) * 272 + tid2 * 4;
            char* prow8 = prow0 + 8 * 272;
            #pragma unroll
            for (int t4 = 0; t4 < 4; t4++) {
                unsigned b0, b1, b2, b3;
                ldsm_x4(sbase + OFF_QTC + (unsigned)((t4 * 32 + lane) * 16),
                        b0, b1, b2, b3);
                #pragma unroll
                for (int tt = 0; tt < 4; tt++) {
                    unsigned bb = (tt == 0) ? b0 : (tt == 1) ? b1 : (tt == 2) ? b2 : b3;
                    int t = t4 * 4 + tt;
                    float d0, d1, d2, d3;
                    mma16808(d0, d1, d2, d3, pba0, pba1, bb);
                    int iA = t * 8 + tid2 * 2;
                    float2 mf = __half22float2(*(const __half2*)(smx + iA));
                    float f0 = fmaf(d0, L2E, -mf.x);
                    float f1 = fmaf(d1, L2E, -mf.y);
                    float f2 = fmaf(d2, L2E, -mf.x);
                    float f3 = fmaf(d3, L2E, -mf.y);
                    __half2 h01 = __floats2half2_rn(f0, f1);
                    __half2 h23 = __floats2half2_rn(f2, f3);
                    unsigned e01 = ex2_f16x2(*(unsigned*)&h01);
                    unsigned e23 = ex2_f16x2(*(unsigned*)&h23);
                    *(unsigned*)(prow0 + t * 16) = e01;
                    *(unsigned*)(prow8 + t * 16) = e23;
                    __half2 cs = __hadd2(*(__half2*)&e01, *(__half2*)&e23);
                    unsigned csu = *(unsigned*)&cs;
                    unsigned o4  = __shfl_xor_sync(0xffffffffu, csu, 4);
                    cs = __hadd2(cs, *(__half2*)&o4);  csu = *(unsigned*)&cs;
                    unsigned o8  = __shfl_xor_sync(0xffffffffu, csu, 8);
                    cs = __hadd2(cs, *(__half2*)&o8);  csu = *(unsigned*)&cs;
                    unsigned o16 = __shfl_xor_sync(0xffffffffu, csu, 16);
                    cs = __hadd2(cs, *(__half2*)&o16); csu = *(unsigned*)&cs;
                    if (gid == 0)
                        *(unsigned*)(pb + wid * 128 + iA) = csu;
                }
            }
        }
        __syncthreads();

        // reduce l partials -> 1/l
        if (tid < 128) {
            float s = 0.f;
            #pragma unroll
            for (int w = 0; w < 16; w++)
                s += __half2float(((__half*)(smem + OFF_KT))[w * 128 + tid]);
            ((float*)(smem + OFF_SL))[tid] = 1.0f / s;
        }
        __syncthreads();

        // fold 1/l_i into V row i (scalar per 128B row, conflict-free)
        {
            const float* sl = (const float*)(smem + OFF_SL);
            for (int idx = tid; idx < 4096; idx += 512) {
                int rl = idx >> 5, w = idx & 31;
                __half2* vv = (__half2*)(smem + OFF_V + ((chunk << 7) + rl) * 144 + w * 4);
                *vv = __hmul2(*vv, __float2half2_rn(sl[rl]));
            }
        }
        __syncthreads();

        // O-GEMM K-chunk: acc += V'[c][k] * P^T[j][k]  (A via trans ldmatrix)
        {
            unsigned aaddr = abase + (unsigned)(chunk * 128) * 144u;
            #pragma unroll
            for (int kk = 0; kk < 8; kk++) {
                unsigned a0, a1, a2, a3;
                ldsm_x4_t(aaddr + (unsigned)(kk * 16) * 144u, a0, a1, a2, a3);
                #pragma unroll
                for (int g = 0; g < 4; g++) {
                    unsigned b0, b1, b2, b3;
                    ldsm_x4(bbase + (unsigned)g * (16u * 272u) + (unsigned)kk * 32u,
                            b0, b1, b2, b3);
                    mma16816(acc[2 * g],     a0, a1, a2, a3, b0, b1);
                    mma16816(acc[2 * g + 1], a0, a1, a2, a3, b2, b3);
                }
            }
        }
        __syncthreads();
    }

    // ---- stage O fp16 in smem (reuse PT, stride 264 halfs), coalesced store ----
    {
        __half* so = (__half*)(smem + OFF_PT);
        int crow = mc * 16 + gid;
        int jb2  = jc * 64 + tid2 * 2;
        #pragma unroll
        for (int nt = 0; nt < 8; nt++) {
            int j = jb2 + nt * 8;
            *(__half2*)(so + crow * 264 + j)       = __floats2half2_rn(acc[nt][0], acc[nt][1]);
            *(__half2*)(so + (crow + 8) * 264 + j) = __floats2half2_rn(acc[nt][2], acc[nt][3]);
        }
        __syncthreads();
        for (int idx = tid; idx < 2048; idx += 512) {
            int c = idx >> 5, seg = idx & 31;
            ((uint4*)(o0 + (c << 16)))[seg] = *(uint4*)(so + c * 264 + seg * 8);
        }
    }
}

// ---- K3: out = gamma*(h_out + w_out) + x (fp16 h/w, fp32 out) ----
__global__ void combine_kernel(const float* __restrict__ x,
                               const float* __restrict__ gamma,
                               float* __restrict__ out)
{
    __shared__ __half t[32][33];
    int plane = blockIdx.z;
    const __half* hT = g_hT + ((long)plane << 16);
    const __half* wf = g_w  + ((long)plane << 16);
    const float*  xp = x    + ((long)plane << 16);
    float*        op = out  + ((long)plane << 16);
    int h0 = blockIdx.y << 5, w0 = blockIdx.x << 5;
    int tx = threadIdx.x, ty = threadIdx.y;
    float g = gamma[0];
    #pragma unroll
    for (int yy = 0; yy < 32; yy += 8)
        t[ty + yy][tx] = hT[(w0 + ty + yy) * 256 + h0 + tx];
    __syncthreads();
    #pragma unroll
    for (int yy = 0; yy < 32; yy += 8) {
        int idx = (h0 + ty + yy) * 256 + w0 + tx;
        op[idx] = fmaf(g, __half2float(t[tx][ty + yy]) + __half2float(wf[idx]), xp[idx]);
    }
}

extern "C" void kernel_launch(void* const* d_in, const int* in_sizes, int n_in,
                              void* d_out, int out_size) {
    const float* x     = (const float*)d_in[0];
    const float* Wq    = (const float*)d_in[1];
    const float* bq    = (const float*)d_in[2];
    const float* Wk    = (const float*)d_in[3];
    const float* bk    = (const float*)d_in[4];
    const float* Wv    = (const float*)d_in[5];
    const float* bv    = (const float*)d_in[6];
    const float* gamma = (const float*)d_in[7];
    float* out = (float*)d_out;

    cudaFuncSetAttribute(attn_kernel,
                         cudaFuncAttributeMaxDynamicSharedMemorySize, ATTN_SMEM);

    proj_qk<<<2048, 256>>>(x, Wq, bq, Wk, bk);
    proj_v<<<2048, 512>>>(x, Wv, bv);
    attn_kernel<<<4096, 512, ATTN_SMEM>>>();
    combine_kernel<<<dim3(8, 8, 512), dim3(32, 8)>>>(x, gamma, out);
}